// round 14
// baseline (speedup 1.0000x reference)
#include <cuda_runtime.h>
#include <cstdint>

// Problem constants
#define BB   256
#define TT   512
#define DIN  64
#define HIDN 64
#define NBAS 10
#define KDIM (DIN*NBAS)   // 640
#define NCLS 2

// Kernel config: 2 rows/CTA, 1024 threads, 128 CTAs, 32 warps (8/SMSP)
#define RPB   2
#define NBLK  (BB/RPB)          // 128 blocks
#define NTHR  1024
#define SPLIT 32                // split-k groups == warps
#define KPER  (KDIM/SPLIT)      // 20 k-iters per thread
#define REDW  66                // padded s_red row: conflict-free for this mapping

__device__ __forceinline__ float fast_tanh(float y) {
    float e = __expf(2.0f * y);
    return 1.0f - __fdividef(2.0f, e + 1.0f);
}
__device__ __forceinline__ float fast_sigmoid(float y) {
    return __fdividef(1.0f, 1.0f + __expf(-y));
}
__device__ __forceinline__ unsigned long long pack_dup(float p) {
    unsigned long long r;
    asm("mov.b64 %0, {%1, %1};" : "=l"(r) : "r"(__float_as_uint(p)));
    return r;
}
__device__ __forceinline__ void fma2(unsigned long long& d,
                                     unsigned long long a,
                                     unsigned long long b) {
    asm("fma.rn.f32x2 %0, %1, %2, %0;" : "+l"(d) : "l"(a), "l"(b));
}

__global__ __launch_bounds__(NTHR, 1) void node_rnn_fused_kernel(
    const float* __restrict__ x,
    const float* __restrict__ c0, const float* __restrict__ w0, const float* __restrict__ C0,
    const float* __restrict__ c1, const float* __restrict__ w1, const float* __restrict__ C1,
    const float* __restrict__ c2, const float* __restrict__ w2, const float* __restrict__ C2,
    const float* __restrict__ Whead, const float* __restrict__ bhead,
    float* __restrict__ out)
{
    __shared__ float s_x  [RPB][DIN];
    __shared__ float s_val[RPB][HIDN];
    __shared__ float s_phi[RPB][KDIM];
    __shared__ float s_red[SPLIT][RPB][REDW];
    __shared__ float s_c[3][NBAS], s_iw[3][NBAS];
    __shared__ float s_W[HIDN * NCLS];
    __shared__ float s_b[NCLS];

    const int tid = threadIdx.x;
    const int r0  = blockIdx.x * RPB;

    // --- startup loads (independent, high MLP) ---
    if (tid < NBAS)        { s_c[0][tid]      = c0[tid];      s_iw[0][tid]      = __frcp_rn(w0[tid]); }
    else if (tid < 2*NBAS) { int k = tid-NBAS;   s_c[1][k] = c1[k]; s_iw[1][k] = __frcp_rn(w1[k]); }
    else if (tid < 3*NBAS) { int k = tid-2*NBAS; s_c[2][k] = c2[k]; s_iw[2][k] = __frcp_rn(w2[k]); }

    if (tid >= 128 && tid < 128 + HIDN * NCLS) s_W[tid - 128] = Whead[tid - 128];
    if (tid >= 384 && tid < 384 + NCLS)        s_b[tid - 384] = bhead[tid - 384];

    if (tid >= 896) {
        int t = tid - 896;               // 0..127
        int r = t >> 6, i = t & 63;
        s_x[r][i] = x[(size_t)(r0 + r) * (TT * DIN) + (size_t)(TT - 1) * DIN + i];
    }

    // GEMM mapping: 2 output columns per thread, split-k group == warp
    const int q2  = tid & 31;        // column pair: cols 2q2, 2q2+1
    const int g   = tid >> 5;        // warp id == split-k group 0..31
    const int kk0 = g * KPER;

    // reduce mapping: 8 threads per (row,unit); warp covers 4 pairs
    const int wid  = g;
    const int lane = tid & 31;
    const int part = lane & 7;                 // 0..7
    const int idx  = lane >> 3;                // 0..3
    const int rr   = idx & 1;                  // row
    const int uu   = (wid << 1) + (idx >> 1);  // hidden unit 0..63
    // basis split over 8 threads: parts 0,1 take 2 each; parts 2..7 take 1
    const int kbeg = (part < 2) ? part * 2 : part + 2;
    const int kcnt = (part < 2) ? 2 : 1;

    const float* Cs[3] = { C0, C1, C2 };

    // ---- stage-0 coefficient loads: packed column pairs, 20 x 8B = 40 regs ----
    unsigned long long cv[KPER];
    #pragma unroll
    for (int j = 0; j < KPER; ++j)
        cv[j] = *reinterpret_cast<const unsigned long long*>(
                    C0 + (size_t)(kk0 + j) * HIDN + 2 * q2);

    __syncthreads();   // consts + x rows ready

    // ---- stage-0 phi from x ----
    #pragma unroll
    for (int it = tid; it < RPB * KDIM; it += NTHR) {
        int r = it / KDIM, rem = it - r * KDIM;
        int i = rem / NBAS, k = rem - i * NBAS;
        s_phi[r][rem] = fast_tanh((s_x[r][i] - s_c[0][k]) * s_iw[0][k]);
    }
    __syncthreads();

    #pragma unroll 1
    for (int stage = 0; stage < 3; ++stage) {
        // ---- split-k GEMM: packed f32x2, coeff pair in regs, phi broadcast LDS ----
        unsigned long long A0 = 0ull, A1 = 0ull;   // rows 0,1 x cols (2q2, 2q2+1)

        #pragma unroll
        for (int jj = 0; jj < KPER / 4; ++jj) {
            float4 p0 = *reinterpret_cast<const float4*>(&s_phi[0][kk0 + 4 * jj]);
            float4 p1 = *reinterpret_cast<const float4*>(&s_phi[1][kk0 + 4 * jj]);
            #pragma unroll
            for (int e = 0; e < 4; ++e) {
                unsigned long long c2p = cv[4 * jj + e];
                float pa = (e == 0) ? p0.x : (e == 1) ? p0.y : (e == 2) ? p0.z : p0.w;
                float pb = (e == 0) ? p1.x : (e == 1) ? p1.y : (e == 2) ? p1.z : p1.w;
                fma2(A0, c2p, pack_dup(pa));
                fma2(A1, c2p, pack_dup(pb));
            }
        }

        // ---- prefetch NEXT stage's coefficients (cv regs now dead) ----
        if (stage < 2) {
            const float* __restrict__ Cn = Cs[stage + 1];
            #pragma unroll
            for (int j = 0; j < KPER; ++j)
                cv[j] = *reinterpret_cast<const unsigned long long*>(
                            Cn + (size_t)(kk0 + j) * HIDN + 2 * q2);
        }

        // ---- write partials (8B stores; REDW=66 keeps 8B alignment) ----
        *reinterpret_cast<unsigned long long*>(&s_red[g][0][2 * q2]) = A0;
        *reinterpret_cast<unsigned long long*>(&s_red[g][1][2 * q2]) = A1;
        __syncthreads();

        // ---- fused: reduce (8 thr/unit x 4 partials) + activation + phi ----
        {
            float v = 0.0f;
            #pragma unroll
            for (int jj = 0; jj < 4; ++jj)
                v += s_red[part + 8 * jj][rr][uu];
            v += __shfl_xor_sync(0xffffffffu, v, 1);
            v += __shfl_xor_sync(0xffffffffu, v, 2);
            v += __shfl_xor_sync(0xffffffffu, v, 4);   // all 8 group threads hold sum

            float h = (stage == 0) ? v : fast_sigmoid(v);

            if (stage < 2) {
                const int st = stage + 1;
                #pragma unroll
                for (int t = 0; t < 2; ++t) {
                    if (t < kcnt) {
                        int k = kbeg + t;
                        s_phi[rr][uu * NBAS + k] =
                            fast_tanh((h - s_c[st][k]) * s_iw[st][k]);
                    }
                }
            } else {
                if (part == 0) s_val[rr][uu] = h;
            }
        }
        __syncthreads();
    }

    // ---- head: logits[r][c] = h . W[:,c] + b[c] ----
    if (tid < RPB * NCLS) {
        int r = tid / NCLS, c = tid % NCLS;
        float s = s_b[c];
        #pragma unroll
        for (int o = 0; o < HIDN; ++o)
            s = fmaf(s_val[r][o], s_W[o * NCLS + c], s);
        out[(r0 + r) * NCLS + c] = s;
    }
}

extern "C" void kernel_launch(void* const* d_in, const int* in_sizes, int n_in,
                              void* d_out, int out_size) {
    (void)in_sizes; (void)n_in; (void)out_size;
    const float* x  = (const float*)d_in[0];
    const float* c0 = (const float*)d_in[1];
    const float* w0 = (const float*)d_in[2];
    const float* C0 = (const float*)d_in[3];
    const float* c1 = (const float*)d_in[4];
    const float* w1 = (const float*)d_in[5];
    const float* C1 = (const float*)d_in[6];
    const float* c2 = (const float*)d_in[7];
    const float* w2 = (const float*)d_in[8];
    const float* C2 = (const float*)d_in[9];
    const float* W  = (const float*)d_in[10];
    const float* b  = (const float*)d_in[11];
    float* out = (float*)d_out;

    node_rnn_fused_kernel<<<NBLK, NTHR>>>(x, c0, w0, C0, c1, w1, C1,
                                          c2, w2, C2, W, b, out);
}